// round 6
// baseline (speedup 1.0000x reference)
#include <cuda_runtime.h>
#include <cstdint>

// ---------------------------------------------------------------------------
// local_graph_creator: adj = relu(tanh(3*(vec1@gEmb.T - gEmb@vec1.T))),
// per-row top-20 (value desc, index asc) binary mask applied.
//
// Exact-output structure (rel_err == 0.0 across rounds 1-5): each output row
// is zeros plus satval at the 20 smallest column indices whose tanh saturates
// (bits == satval). Only an exact N x 256 strip of scores is needed; rows
// with <20 saturated strip entries go to an exact full-row fallback.
//
// This round: 400MB zero of d_out via TMA bulk stores (cp.async.bulk,
// no per-byte STG issue cost) on a forked stream, overlapping prep+strip.
//
//   main stream:  prep -> strip ---------------+-> scatter -> fallback
//   fork stream:  zero_out (TMA bulk) ---------+   (join via event)
// ---------------------------------------------------------------------------

#define MAX_NPAD 10112

__device__ float g_Xt[128 * MAX_NPAD];     // [k][i]  X = [vec1 | -gEmb]
__device__ float g_Yt[128 * MAX_NPAD];     // [k][i]  Y = [gEmb  |  vec1]
__device__ unsigned g_maskS[MAX_NPAD * 8]; // strip tie bitmask (256 cols/row)
__device__ int g_fb_cnt;
__device__ int g_fb_list[MAX_NPAD];

__device__ __forceinline__ float tanh_xla(float x) {
    const float kClamp = 7.99881172180175781f;
    float ax = fabsf(x);
    float xc = fminf(fmaxf(x, -kClamp), kClamp);
    float x2 = xc * xc;
    float p = -2.76076847742355e-16f;
    p = fmaf(x2, p, 2.00018790482477e-13f);
    p = fmaf(x2, p, -8.60467152213735e-11f);
    p = fmaf(x2, p, 5.12229709037114e-08f);
    p = fmaf(x2, p, 1.48572235717979e-05f);
    p = fmaf(x2, p, 6.37261928875436e-04f);
    p = fmaf(x2, p, 4.89352455891786e-03f);
    p = xc * p;
    float q = fmaf(x2, 1.19825839466702e-06f, 1.18534705686654e-04f);
    q = fmaf(x2, q, 2.26843463243900e-03f);
    q = fmaf(x2, q, 4.89352518554385e-03f);
    float r = p / q;
    return (ax < 0.0004f) ? x : r;
}

__device__ __forceinline__ float sat_val() { return tanh_xla(8.0f); }

__device__ __forceinline__ void cp_async16(uint32_t saddr, const void* gaddr) {
    asm volatile("cp.async.cg.shared.global [%0], [%1], 16;" ::
                 "r"(saddr), "l"(gaddr));
}

// ---------------------------------------------------------------------------
// zero_out: TMA bulk-store zero fill. Each CTA zeroes a 64KB smem buffer once
// and streams it to its strided set of 64KB global chunks in one bulk_group.
// ---------------------------------------------------------------------------
__global__ __launch_bounds__(256) void zero_out_kernel(float* __restrict__ out,
                                                       size_t total_bytes) {
    extern __shared__ __align__(16) float4 zbuf[];  // 64KB = 4096 float4
    const int t = threadIdx.x;
    const float4 z = make_float4(0.0f, 0.0f, 0.0f, 0.0f);
#pragma unroll
    for (int i = 0; i < 16; i++) zbuf[i * 256 + t] = z;
    __syncthreads();
    asm volatile("fence.proxy.async.shared::cta;" ::: "memory");

    if (t == 0) {
        uint32_t saddr = (uint32_t)__cvta_generic_to_shared(zbuf);
        const size_t CH = 65536;
        size_t nch = (total_bytes + CH - 1) / CH;
        for (size_t c = blockIdx.x; c < nch; c += gridDim.x) {
            size_t off = c * CH;
            size_t rem = total_bytes - off;
            uint32_t sz = (uint32_t)(rem < CH ? rem : CH);
            asm volatile(
                "cp.async.bulk.global.shared::cta.bulk_group [%0], [%1], %2;" ::
                "l"((char*)out + off), "r"(saddr), "r"(sz) : "memory");
        }
        asm volatile("cp.async.bulk.commit_group;" ::: "memory");
        asm volatile("cp.async.bulk.wait_group 0;" ::: "memory");
    }
}

// ---------------------------------------------------------------------------
// prep: 64 rows per block; vec1 via smem-resident fc1_w^T; coalesced
// transposed packing of Xt/Yt through smem. Zeroes fallback counter.
// ---------------------------------------------------------------------------
__global__ __launch_bounds__(256) void prep_kernel(
    const int* __restrict__ idx, const float* __restrict__ gEmb,
    const float* __restrict__ embW, const float* __restrict__ fc1w,
    const float* __restrict__ fc1b, int N, int npad) {
    __shared__ float ws[64 * 65];   // phase A: fc1w^T; phase B/C: gEmb
    __shared__ float sv[64 * 65];   // vec1 transposed [d][i_local]
    __shared__ float bs[64];
    const int t = threadIdx.x;
    const int bi0 = blockIdx.x * 64;

    if (blockIdx.x == 0 && t == 0) g_fb_cnt = 0;

    for (int e = t; e < 64 * 64; e += 256) {
        int d = e >> 6, k = e & 63;
        ws[k * 65 + d] = fc1w[e];
    }
    if (t < 64) bs[t] = fc1b[t];
    __syncthreads();

    const int d = t & 63;
    const int rq = t >> 6;
#pragma unroll
    for (int rr = 0; rr < 16; rr++) {
        int il = rr * 4 + rq;
        int i = bi0 + il;
        float v = 0.0f;
        if (i < N) {
            int src = idx[i];
            const float* er = embW + (size_t)src * 64;
            float acc = 0.0f;
#pragma unroll
            for (int k = 0; k < 64; k++) acc = fmaf(er[k], ws[k * 65 + d], acc);
            acc += bs[d];
            v = tanh_xla(3.0f * acc);
        }
        sv[d * 65 + il] = v;
    }
    __syncthreads();

#pragma unroll
    for (int rr = 0; rr < 16; rr++) {
        int il = rr * 4 + rq;
        int i = bi0 + il;
        float g = (i < N) ? gEmb[(size_t)i * 64 + d] : 0.0f;
        ws[d * 65 + il] = g;
    }
    __syncthreads();

#pragma unroll
    for (int p = 0; p < 8; p++) {
        int e = p * 256 + t;
        int dd = e >> 4;
        int i4 = (e & 15) * 4;
        float4 xv, yv;
        if (dd < 64) {
            xv.x = sv[dd * 65 + i4 + 0]; xv.y = sv[dd * 65 + i4 + 1];
            xv.z = sv[dd * 65 + i4 + 2]; xv.w = sv[dd * 65 + i4 + 3];
            yv.x = ws[dd * 65 + i4 + 0]; yv.y = ws[dd * 65 + i4 + 1];
            yv.z = ws[dd * 65 + i4 + 2]; yv.w = ws[dd * 65 + i4 + 3];
        } else {
            int dl = dd - 64;
            xv.x = -ws[dl * 65 + i4 + 0]; xv.y = -ws[dl * 65 + i4 + 1];
            xv.z = -ws[dl * 65 + i4 + 2]; xv.w = -ws[dl * 65 + i4 + 3];
            yv.x = sv[dl * 65 + i4 + 0];  yv.y = sv[dl * 65 + i4 + 1];
            yv.z = sv[dl * 65 + i4 + 2];  yv.w = sv[dl * 65 + i4 + 3];
        }
        *(float4*)&g_Xt[(size_t)dd * npad + bi0 + i4] = xv;
        *(float4*)&g_Yt[(size_t)dd * npad + bi0 + i4] = yv;
    }
}

// ---------------------------------------------------------------------------
// strip: 64 rows x 128 cols per CTA, grid (2, npad/64). Whole K=128 in smem.
// Per-element k-ascending fp32 fmaf chain, bit-identical to prior rounds.
// Emits saturation bitmask words (cols bn..bn+127 -> words (bn>>5)..+3).
// ---------------------------------------------------------------------------
__global__ __launch_bounds__(256, 2) void strip_kernel(int npad) {
    const int bm = blockIdx.y * 64;
    const int bn = blockIdx.x * 128;

    extern __shared__ float sm[];
    float* Asf = sm;           // [k][r] 128 x 64
    float* Bsf = sm + 8192;    // [k][r] 128 x 128

    const int t = threadIdx.x;
    const int tx = t & 15, ty = t >> 4;

    {
        const float4* Xv = reinterpret_cast<const float4*>(g_Xt);
        const float4* Yv = reinterpret_cast<const float4*>(g_Yt);
        uint32_t As_s = (uint32_t)__cvta_generic_to_shared(Asf);
        uint32_t Bs_s = (uint32_t)__cvta_generic_to_shared(Bsf);
        const int np4 = npad >> 2;
        const int bm4 = bm >> 2, bn4 = bn >> 2;
#pragma unroll
        for (int e = 0; e < 8; e++) {
            int q = e * 256 + t;      // 0..2047
            int k = q >> 4;           // 0..127
            int r4 = q & 15;
            cp_async16(As_s + q * 16, &Xv[(size_t)k * np4 + bm4 + r4]);
        }
#pragma unroll
        for (int e = 0; e < 16; e++) {
            int q = e * 256 + t;      // 0..4095
            int k = q >> 5;
            int r4 = q & 31;
            cp_async16(Bs_s + q * 16, &Yv[(size_t)k * np4 + bn4 + r4]);
        }
        asm volatile("cp.async.commit_group;");
        asm volatile("cp.async.wait_group 0;");
    }
    __syncthreads();

    float acc[4][8];
#pragma unroll
    for (int i = 0; i < 4; i++)
#pragma unroll
        for (int j = 0; j < 8; j++) acc[i][j] = 0.0f;

#pragma unroll 4
    for (int k = 0; k < 128; k++) {
        const float* ak = Asf + k * 64;
        const float* bk = Bsf + k * 128;
        float4 a0 = *(const float4*)(ak + ty * 4);
        float4 b0 = *(const float4*)(bk + tx * 4);
        float4 b1 = *(const float4*)(bk + 64 + tx * 4);
        float ra[4] = {a0.x, a0.y, a0.z, a0.w};
        float rb[8] = {b0.x, b0.y, b0.z, b0.w, b1.x, b1.y, b1.z, b1.w};
#pragma unroll
        for (int i = 0; i < 4; i++)
#pragma unroll
            for (int j = 0; j < 8; j++)
                acc[i][j] = fmaf(ra[i], rb[j], acc[i][j]);
    }

#pragma unroll
    for (int i = 0; i < 4; i++)
#pragma unroll
        for (int j = 0; j < 8; j++) acc[i][j] = tanh_xla(3.0f * acc[i][j]);

    __syncthreads();  // As/Bs dead

    unsigned* mUw = reinterpret_cast<unsigned*>(sm);  // [64][32] nibbles
    const unsigned satb = __float_as_uint(sat_val());

#pragma unroll
    for (int ii = 0; ii < 4; ii++) {
        int r = ty * 4 + ii;
#pragma unroll
        for (int q = 0; q < 2; q++) {
            unsigned nib = 0;
#pragma unroll
            for (int b = 0; b < 4; b++)
                nib |= (__float_as_uint(acc[ii][q * 4 + b]) == satb) << b;
            mUw[r * 32 + 16 * q + tx] = nib;
        }
    }
    __syncthreads();

    {
        int r = t >> 2, ww = t & 3;
        unsigned wd = 0;
#pragma unroll
        for (int b = 0; b < 8; b++) wd |= mUw[r * 32 + ww * 8 + b] << (4 * b);
        g_maskS[(size_t)(bm + r) * 8 + (bn >> 5) + ww] = wd;
    }
}

// ---------------------------------------------------------------------------
// topk_scatter: warp per row. Scatter satval at the 20 smallest set bits of
// the 256-col strip mask into the (pre-zeroed) row. <20 -> fallback list.
// ---------------------------------------------------------------------------
__global__ __launch_bounds__(256) void topk_scatter_kernel(
    float* __restrict__ out, int N) {
    const int row = blockIdx.x * 8 + (threadIdx.x >> 5);
    const int lane = threadIdx.x & 31;
    if (row >= N) return;

    unsigned w = (lane < 8) ? g_maskS[(size_t)row * 8 + lane] : 0u;
    int c = __popc(w);
    int incl = c;
#pragma unroll
    for (int s = 1; s < 32; s <<= 1) {
        int o = __shfl_up_sync(0xffffffffu, incl, s);
        if (lane >= s) incl += o;
    }
    int excl = incl - c;
    int total = __shfl_sync(0xffffffffu, incl, 31);

    if (total >= 20) {
        const float sv = sat_val();
        float* rowp = out + (size_t)row * N;
        int base = excl;
        unsigned ww = w;
        while (ww && base < 20) {
            int b = __ffs(ww) - 1;
            ww &= ww - 1;
            rowp[lane * 32 + b] = sv;
            base++;
        }
    } else if (lane == 0) {
        int p = atomicAdd(&g_fb_cnt, 1);
        g_fb_list[p] = row;
    }
}

// ---------------------------------------------------------------------------
// fallback: exact full-row recompute + general top-20 (expected 0 rows).
// ---------------------------------------------------------------------------
__global__ __launch_bounds__(256) void fallback_kernel(float* __restrict__ out,
                                                       int N, int npad) {
    __shared__ float sX[128];
    __shared__ __align__(16) float srow[10016];
    __shared__ unsigned long long red[256];
    __shared__ int selIdx[20];
    __shared__ float selVal[20];

    const int t = threadIdx.x;
    const int cnt = g_fb_cnt;

    for (int ri = blockIdx.x; ri < cnt; ri += gridDim.x) {
        const int row = g_fb_list[ri];
        if (t < 128) sX[t] = g_Xt[(size_t)t * npad + row];
        __syncthreads();

        for (int j = t; j < N; j += 256) {
            float a = 0.0f;
#pragma unroll 4
            for (int k = 0; k < 128; k++)
                a = fmaf(sX[k], g_Yt[(size_t)k * npad + j], a);
            srow[j] = fmaxf(tanh_xla(3.0f * a), 0.0f);
        }
        __syncthreads();

        unsigned long long cand[20];
#pragma unroll
        for (int c = 0; c < 20; c++) cand[c] = 0ull;
        unsigned long long curMin = 0ull;
        for (int q = t; q < N; q += 256) {
            unsigned vb = __float_as_uint(srow[q]);
            if (vb == 0x80000000u) vb = 0u;
            unsigned long long key =
                ((unsigned long long)vb << 32) |
                (unsigned long long)(0xFFFFFFFFu - (unsigned)q);
            if (key > curMin) {
                bool done = false;
#pragma unroll
                for (int c = 0; c < 20; c++) {
                    if (!done && cand[c] == curMin) {
                        cand[c] = key;
                        done = true;
                    }
                }
                unsigned long long m = cand[0];
#pragma unroll
                for (int c = 1; c < 20; c++) m = (cand[c] < m) ? cand[c] : m;
                curMin = m;
            }
        }
        for (int it = 0; it < 20; it++) {
            unsigned long long m = cand[0];
#pragma unroll
            for (int c = 1; c < 20; c++) m = (cand[c] > m) ? cand[c] : m;
            red[t] = m;
            __syncthreads();
            for (int s = 128; s >= 32; s >>= 1) {
                if (t < s) {
                    unsigned long long o = red[t + s];
                    if (o > red[t]) red[t] = o;
                }
                __syncthreads();
            }
            if (t < 32) {
                unsigned long long g = red[t];
#pragma unroll
                for (int s = 16; s; s >>= 1) {
                    unsigned long long o = __shfl_xor_sync(0xffffffffu, g, s);
                    if (o > g) g = o;
                }
                if (t == 0) red[0] = g;
            }
            __syncthreads();
            unsigned long long g = red[0];
            if (t == 0) {
                if (g != 0ull) {
                    selIdx[it] =
                        (int)(0xFFFFFFFFu - (unsigned)(g & 0xFFFFFFFFull));
                    selVal[it] = __uint_as_float((unsigned)(g >> 32));
                } else {
                    selIdx[it] = 0;
                    selVal[it] = 0.0f;
                }
            }
            if (g != 0ull) {
#pragma unroll
                for (int c = 0; c < 20; c++)
                    if (cand[c] == g) cand[c] = 0ull;
            }
            __syncthreads();
        }
        if (t < 20) out[(size_t)row * N + selIdx[t]] = selVal[t];
        __syncthreads();
    }
}

// ---------------------------------------------------------------------------
extern "C" void kernel_launch(void* const* d_in, const int* in_sizes, int n_in,
                              void* d_out, int out_size) {
    const int* idx = (const int*)d_in[0];
    const float* gEmb = (const float*)d_in[1];
    const float* embW = (const float*)d_in[2];
    const float* fc1w = (const float*)d_in[3];
    const float* fc1b = (const float*)d_in[4];
    float* out = (float*)d_out;

    int N = in_sizes[0];
    int npad = ((N + 127) / 128) * 128;
    int tiles64 = npad / 64;

    static cudaStream_t s_fork = nullptr;
    static cudaEvent_t s_evFork = nullptr, s_evJoin = nullptr;
    static bool s_init = false;
    if (!s_init) {
        cudaFuncSetAttribute(strip_kernel,
                             cudaFuncAttributeMaxDynamicSharedMemorySize,
                             98304);
        cudaFuncSetAttribute(zero_out_kernel,
                             cudaFuncAttributeMaxDynamicSharedMemorySize,
                             65536);
        cudaStreamCreateWithFlags(&s_fork, cudaStreamNonBlocking);
        cudaEventCreateWithFlags(&s_evFork, cudaEventDisableTiming);
        cudaEventCreateWithFlags(&s_evJoin, cudaEventDisableTiming);
        s_init = true;
    }

    // fork: zero d_out via TMA bulk stores on side stream, overlapping
    // prep + strip on the main stream
    cudaEventRecord(s_evFork, 0);
    cudaStreamWaitEvent(s_fork, s_evFork, 0);
    zero_out_kernel<<<296, 256, 65536, s_fork>>>(
        out, (size_t)out_size * sizeof(float));
    cudaEventRecord(s_evJoin, s_fork);

    prep_kernel<<<npad / 64, 256>>>(idx, gEmb, embW, fc1w, fc1b, N, npad);
    strip_kernel<<<dim3(2, tiles64), 256, 98304>>>(npad);

    // join: scatter needs the zeroed buffer
    cudaStreamWaitEvent(0, s_evJoin, 0);
    topk_scatter_kernel<<<(N + 7) / 8, 256>>>(out, N);
    fallback_kernel<<<148, 256>>>(out, N, npad);
}

// round 7
// speedup vs baseline: 1.0113x; 1.0113x over previous
#include <cuda_runtime.h>
#include <cstdint>

// ---------------------------------------------------------------------------
// local_graph_creator: adj = relu(tanh(3*(vec1@gEmb.T - gEmb@vec1.T))),
// per-row top-20 (value desc, index asc) binary mask applied.
//
// Exact-output structure (rel_err == 0.0 across rounds 1-6): each output row
// is zeros plus satval at the 20 smallest column indices whose tanh saturates
// (bits == satval). Only an exact N x 256 strip of scores is needed; rows
// with <20 saturated strip entries go to an exact full-row fallback.
//
// Round-6 lesson: memset node and TMA bulk stores both fill at ~2.5 TB/s;
// a wide grid-stride STG.128 loop measured 4.3 TB/s (round 4). So the forked
// zero writer is now that STG kernel.
//
//   main stream:  prep -> strip ---------------+-> scatter -> fallback
//   fork stream:  zero_stg (grid-stride f4) ---+   (join via event)
// ---------------------------------------------------------------------------

#define MAX_NPAD 10112

__device__ float g_Xt[128 * MAX_NPAD];     // [k][i]  X = [vec1 | -gEmb]
__device__ float g_Yt[128 * MAX_NPAD];     // [k][i]  Y = [gEmb  |  vec1]
__device__ unsigned g_maskS[MAX_NPAD * 8]; // strip tie bitmask (256 cols/row)
__device__ int g_fb_cnt;
__device__ int g_fb_list[MAX_NPAD];

__device__ __forceinline__ float tanh_xla(float x) {
    const float kClamp = 7.99881172180175781f;
    float ax = fabsf(x);
    float xc = fminf(fmaxf(x, -kClamp), kClamp);
    float x2 = xc * xc;
    float p = -2.76076847742355e-16f;
    p = fmaf(x2, p, 2.00018790482477e-13f);
    p = fmaf(x2, p, -8.60467152213735e-11f);
    p = fmaf(x2, p, 5.12229709037114e-08f);
    p = fmaf(x2, p, 1.48572235717979e-05f);
    p = fmaf(x2, p, 6.37261928875436e-04f);
    p = fmaf(x2, p, 4.89352455891786e-03f);
    p = xc * p;
    float q = fmaf(x2, 1.19825839466702e-06f, 1.18534705686654e-04f);
    q = fmaf(x2, q, 2.26843463243900e-03f);
    q = fmaf(x2, q, 4.89352518554385e-03f);
    float r = p / q;
    return (ax < 0.0004f) ? x : r;
}

__device__ __forceinline__ float sat_val() { return tanh_xla(8.0f); }

__device__ __forceinline__ void cp_async16(uint32_t saddr, const void* gaddr) {
    asm volatile("cp.async.cg.shared.global [%0], [%1], 16;" ::
                 "r"(saddr), "l"(gaddr));
}

// ---------------------------------------------------------------------------
// zero_stg: grid-stride float4 zero fill (the empirically fastest writer:
// 4.3 TB/s at 1250 CTAs in round 4; memset/TMA bulk measured only 2.5 TB/s).
// ---------------------------------------------------------------------------
__global__ __launch_bounds__(256) void zero_stg_kernel(float4* __restrict__ out,
                                                       size_t n4) {
    const float4 z = make_float4(0.0f, 0.0f, 0.0f, 0.0f);
    size_t i = (size_t)blockIdx.x * 256 + threadIdx.x;
    const size_t stride = (size_t)gridDim.x * 256;
    for (; i < n4; i += stride) out[i] = z;
}

// tail handler for non-multiple-of-4 element counts (N*N=1e8 is divisible,
// but keep exactness for any shape)
__global__ void zero_tail_kernel(float* __restrict__ out, size_t from,
                                 size_t total) {
    size_t i = from + blockIdx.x * blockDim.x + threadIdx.x;
    if (i < total) out[i] = 0.0f;
}

// ---------------------------------------------------------------------------
// prep: 64 rows per block; vec1 via smem-resident fc1_w^T; coalesced
// transposed packing of Xt/Yt through smem. Zeroes fallback counter.
// ---------------------------------------------------------------------------
__global__ __launch_bounds__(256) void prep_kernel(
    const int* __restrict__ idx, const float* __restrict__ gEmb,
    const float* __restrict__ embW, const float* __restrict__ fc1w,
    const float* __restrict__ fc1b, int N, int npad) {
    __shared__ float ws[64 * 65];   // phase A: fc1w^T; phase B/C: gEmb
    __shared__ float sv[64 * 65];   // vec1 transposed [d][i_local]
    __shared__ float bs[64];
    const int t = threadIdx.x;
    const int bi0 = blockIdx.x * 64;

    if (blockIdx.x == 0 && t == 0) g_fb_cnt = 0;

    for (int e = t; e < 64 * 64; e += 256) {
        int d = e >> 6, k = e & 63;
        ws[k * 65 + d] = fc1w[e];
    }
    if (t < 64) bs[t] = fc1b[t];
    __syncthreads();

    const int d = t & 63;
    const int rq = t >> 6;
#pragma unroll
    for (int rr = 0; rr < 16; rr++) {
        int il = rr * 4 + rq;
        int i = bi0 + il;
        float v = 0.0f;
        if (i < N) {
            int src = idx[i];
            const float* er = embW + (size_t)src * 64;
            float acc = 0.0f;
#pragma unroll
            for (int k = 0; k < 64; k++) acc = fmaf(er[k], ws[k * 65 + d], acc);
            acc += bs[d];
            v = tanh_xla(3.0f * acc);
        }
        sv[d * 65 + il] = v;
    }
    __syncthreads();

#pragma unroll
    for (int rr = 0; rr < 16; rr++) {
        int il = rr * 4 + rq;
        int i = bi0 + il;
        float g = (i < N) ? gEmb[(size_t)i * 64 + d] : 0.0f;
        ws[d * 65 + il] = g;
    }
    __syncthreads();

#pragma unroll
    for (int p = 0; p < 8; p++) {
        int e = p * 256 + t;
        int dd = e >> 4;
        int i4 = (e & 15) * 4;
        float4 xv, yv;
        if (dd < 64) {
            xv.x = sv[dd * 65 + i4 + 0]; xv.y = sv[dd * 65 + i4 + 1];
            xv.z = sv[dd * 65 + i4 + 2]; xv.w = sv[dd * 65 + i4 + 3];
            yv.x = ws[dd * 65 + i4 + 0]; yv.y = ws[dd * 65 + i4 + 1];
            yv.z = ws[dd * 65 + i4 + 2]; yv.w = ws[dd * 65 + i4 + 3];
        } else {
            int dl = dd - 64;
            xv.x = -ws[dl * 65 + i4 + 0]; xv.y = -ws[dl * 65 + i4 + 1];
            xv.z = -ws[dl * 65 + i4 + 2]; xv.w = -ws[dl * 65 + i4 + 3];
            yv.x = sv[dl * 65 + i4 + 0];  yv.y = sv[dl * 65 + i4 + 1];
            yv.z = sv[dl * 65 + i4 + 2];  yv.w = sv[dl * 65 + i4 + 3];
        }
        *(float4*)&g_Xt[(size_t)dd * npad + bi0 + i4] = xv;
        *(float4*)&g_Yt[(size_t)dd * npad + bi0 + i4] = yv;
    }
}

// ---------------------------------------------------------------------------
// strip: 64 rows x 128 cols per CTA, grid (2, npad/64). Whole K=128 in smem.
// Per-element k-ascending fp32 fmaf chain, bit-identical to prior rounds.
// Emits saturation bitmask words (cols bn..bn+127 -> words (bn>>5)..+3).
// ---------------------------------------------------------------------------
__global__ __launch_bounds__(256, 2) void strip_kernel(int npad) {
    const int bm = blockIdx.y * 64;
    const int bn = blockIdx.x * 128;

    extern __shared__ float sm[];
    float* Asf = sm;           // [k][r] 128 x 64
    float* Bsf = sm + 8192;    // [k][r] 128 x 128

    const int t = threadIdx.x;
    const int tx = t & 15, ty = t >> 4;

    {
        const float4* Xv = reinterpret_cast<const float4*>(g_Xt);
        const float4* Yv = reinterpret_cast<const float4*>(g_Yt);
        uint32_t As_s = (uint32_t)__cvta_generic_to_shared(Asf);
        uint32_t Bs_s = (uint32_t)__cvta_generic_to_shared(Bsf);
        const int np4 = npad >> 2;
        const int bm4 = bm >> 2, bn4 = bn >> 2;
#pragma unroll
        for (int e = 0; e < 8; e++) {
            int q = e * 256 + t;      // 0..2047
            int k = q >> 4;           // 0..127
            int r4 = q & 15;
            cp_async16(As_s + q * 16, &Xv[(size_t)k * np4 + bm4 + r4]);
        }
#pragma unroll
        for (int e = 0; e < 16; e++) {
            int q = e * 256 + t;      // 0..4095
            int k = q >> 5;
            int r4 = q & 31;
            cp_async16(Bs_s + q * 16, &Yv[(size_t)k * np4 + bn4 + r4]);
        }
        asm volatile("cp.async.commit_group;");
        asm volatile("cp.async.wait_group 0;");
    }
    __syncthreads();

    float acc[4][8];
#pragma unroll
    for (int i = 0; i < 4; i++)
#pragma unroll
        for (int j = 0; j < 8; j++) acc[i][j] = 0.0f;

#pragma unroll 4
    for (int k = 0; k < 128; k++) {
        const float* ak = Asf + k * 64;
        const float* bk = Bsf + k * 128;
        float4 a0 = *(const float4*)(ak + ty * 4);
        float4 b0 = *(const float4*)(bk + tx * 4);
        float4 b1 = *(const float4*)(bk + 64 + tx * 4);
        float ra[4] = {a0.x, a0.y, a0.z, a0.w};
        float rb[8] = {b0.x, b0.y, b0.z, b0.w, b1.x, b1.y, b1.z, b1.w};
#pragma unroll
        for (int i = 0; i < 4; i++)
#pragma unroll
            for (int j = 0; j < 8; j++)
                acc[i][j] = fmaf(ra[i], rb[j], acc[i][j]);
    }

#pragma unroll
    for (int i = 0; i < 4; i++)
#pragma unroll
        for (int j = 0; j < 8; j++) acc[i][j] = tanh_xla(3.0f * acc[i][j]);

    __syncthreads();  // As/Bs dead

    unsigned* mUw = reinterpret_cast<unsigned*>(sm);  // [64][32] nibbles
    const unsigned satb = __float_as_uint(sat_val());

#pragma unroll
    for (int ii = 0; ii < 4; ii++) {
        int r = ty * 4 + ii;
#pragma unroll
        for (int q = 0; q < 2; q++) {
            unsigned nib = 0;
#pragma unroll
            for (int b = 0; b < 4; b++)
                nib |= (__float_as_uint(acc[ii][q * 4 + b]) == satb) << b;
            mUw[r * 32 + 16 * q + tx] = nib;
        }
    }
    __syncthreads();

    {
        int r = t >> 2, ww = t & 3;
        unsigned wd = 0;
#pragma unroll
        for (int b = 0; b < 8; b++) wd |= mUw[r * 32 + ww * 8 + b] << (4 * b);
        g_maskS[(size_t)(bm + r) * 8 + (bn >> 5) + ww] = wd;
    }
}

// ---------------------------------------------------------------------------
// topk_scatter: warp per row. Scatter satval at the 20 smallest set bits of
// the 256-col strip mask into the (pre-zeroed) row. <20 -> fallback list.
// ---------------------------------------------------------------------------
__global__ __launch_bounds__(256) void topk_scatter_kernel(
    float* __restrict__ out, int N) {
    const int row = blockIdx.x * 8 + (threadIdx.x >> 5);
    const int lane = threadIdx.x & 31;
    if (row >= N) return;

    unsigned w = (lane < 8) ? g_maskS[(size_t)row * 8 + lane] : 0u;
    int c = __popc(w);
    int incl = c;
#pragma unroll
    for (int s = 1; s < 32; s <<= 1) {
        int o = __shfl_up_sync(0xffffffffu, incl, s);
        if (lane >= s) incl += o;
    }
    int excl = incl - c;
    int total = __shfl_sync(0xffffffffu, incl, 31);

    if (total >= 20) {
        const float sv = sat_val();
        float* rowp = out + (size_t)row * N;
        int base = excl;
        unsigned ww = w;
        while (ww && base < 20) {
            int b = __ffs(ww) - 1;
            ww &= ww - 1;
            rowp[lane * 32 + b] = sv;
            base++;
        }
    } else if (lane == 0) {
        int p = atomicAdd(&g_fb_cnt, 1);
        g_fb_list[p] = row;
    }
}

// ---------------------------------------------------------------------------
// fallback: exact full-row recompute + general top-20 (expected 0 rows).
// ---------------------------------------------------------------------------
__global__ __launch_bounds__(256) void fallback_kernel(float* __restrict__ out,
                                                       int N, int npad) {
    __shared__ float sX[128];
    __shared__ __align__(16) float srow[10016];
    __shared__ unsigned long long red[256];
    __shared__ int selIdx[20];
    __shared__ float selVal[20];

    const int t = threadIdx.x;
    const int cnt = g_fb_cnt;

    for (int ri = blockIdx.x; ri < cnt; ri += gridDim.x) {
        const int row = g_fb_list[ri];
        if (t < 128) sX[t] = g_Xt[(size_t)t * npad + row];
        __syncthreads();

        for (int j = t; j < N; j += 256) {
            float a = 0.0f;
#pragma unroll 4
            for (int k = 0; k < 128; k++)
                a = fmaf(sX[k], g_Yt[(size_t)k * npad + j], a);
            srow[j] = fmaxf(tanh_xla(3.0f * a), 0.0f);
        }
        __syncthreads();

        unsigned long long cand[20];
#pragma unroll
        for (int c = 0; c < 20; c++) cand[c] = 0ull;
        unsigned long long curMin = 0ull;
        for (int q = t; q < N; q += 256) {
            unsigned vb = __float_as_uint(srow[q]);
            if (vb == 0x80000000u) vb = 0u;
            unsigned long long key =
                ((unsigned long long)vb << 32) |
                (unsigned long long)(0xFFFFFFFFu - (unsigned)q);
            if (key > curMin) {
                bool done = false;
#pragma unroll
                for (int c = 0; c < 20; c++) {
                    if (!done && cand[c] == curMin) {
                        cand[c] = key;
                        done = true;
                    }
                }
                unsigned long long m = cand[0];
#pragma unroll
                for (int c = 1; c < 20; c++) m = (cand[c] < m) ? cand[c] : m;
                curMin = m;
            }
        }
        for (int it = 0; it < 20; it++) {
            unsigned long long m = cand[0];
#pragma unroll
            for (int c = 1; c < 20; c++) m = (cand[c] > m) ? cand[c] : m;
            red[t] = m;
            __syncthreads();
            for (int s = 128; s >= 32; s >>= 1) {
                if (t < s) {
                    unsigned long long o = red[t + s];
                    if (o > red[t]) red[t] = o;
                }
                __syncthreads();
            }
            if (t < 32) {
                unsigned long long g = red[t];
#pragma unroll
                for (int s = 16; s; s >>= 1) {
                    unsigned long long o = __shfl_xor_sync(0xffffffffu, g, s);
                    if (o > g) g = o;
                }
                if (t == 0) red[0] = g;
            }
            __syncthreads();
            unsigned long long g = red[0];
            if (t == 0) {
                if (g != 0ull) {
                    selIdx[it] =
                        (int)(0xFFFFFFFFu - (unsigned)(g & 0xFFFFFFFFull));
                    selVal[it] = __uint_as_float((unsigned)(g >> 32));
                } else {
                    selIdx[it] = 0;
                    selVal[it] = 0.0f;
                }
            }
            if (g != 0ull) {
#pragma unroll
                for (int c = 0; c < 20; c++)
                    if (cand[c] == g) cand[c] = 0ull;
            }
            __syncthreads();
        }
        if (t < 20) out[(size_t)row * N + selIdx[t]] = selVal[t];
        __syncthreads();
    }
}

// ---------------------------------------------------------------------------
extern "C" void kernel_launch(void* const* d_in, const int* in_sizes, int n_in,
                              void* d_out, int out_size) {
    const int* idx = (const int*)d_in[0];
    const float* gEmb = (const float*)d_in[1];
    const float* embW = (const float*)d_in[2];
    const float* fc1w = (const float*)d_in[3];
    const float* fc1b = (const float*)d_in[4];
    float* out = (float*)d_out;

    int N = in_sizes[0];
    int npad = ((N + 127) / 128) * 128;
    int tiles64 = npad / 64;
    size_t total = (size_t)out_size;
    size_t n4 = total >> 2;

    static cudaStream_t s_fork = nullptr;
    static cudaEvent_t s_evFork = nullptr, s_evJoin = nullptr;
    static bool s_init = false;
    if (!s_init) {
        cudaFuncSetAttribute(strip_kernel,
                             cudaFuncAttributeMaxDynamicSharedMemorySize,
                             98304);
        cudaStreamCreateWithFlags(&s_fork, cudaStreamNonBlocking);
        cudaEventCreateWithFlags(&s_evFork, cudaEventDisableTiming);
        cudaEventCreateWithFlags(&s_evJoin, cudaEventDisableTiming);
        s_init = true;
    }

    // fork: zero d_out via grid-stride STG.128 on side stream, overlapping
    // prep + strip on the main stream
    cudaEventRecord(s_evFork, 0);
    cudaStreamWaitEvent(s_fork, s_evFork, 0);
    zero_stg_kernel<<<1250, 256, 0, s_fork>>>((float4*)out, n4);
    if (total & 3) {
        zero_tail_kernel<<<1, 256, 0, s_fork>>>(out, n4 * 4, total);
    }
    cudaEventRecord(s_evJoin, s_fork);

    prep_kernel<<<npad / 64, 256>>>(idx, gEmb, embW, fc1w, fc1b, N, npad);
    strip_kernel<<<dim3(2, tiles64), 256, 98304>>>(npad);

    // join: scatter needs the zeroed buffer
    cudaStreamWaitEvent(0, s_evJoin, 0);
    topk_scatter_kernel<<<(N + 7) / 8, 256>>>(out, N);
    fallback_kernel<<<148, 256>>>(out, N, npad);
}

// round 8
// speedup vs baseline: 1.1049x; 1.0925x over previous
#include <cuda_runtime.h>
#include <cstdint>

// ---------------------------------------------------------------------------
// local_graph_creator: adj = relu(tanh(3*(vec1@gEmb.T - gEmb@vec1.T))),
// per-row top-20 (value desc, index asc) binary mask applied.
//
// Exact-output structure (rel_err == 0.0 across rounds 1-7): each output row
// is zeros plus satval at the 20 smallest column indices whose tanh saturates
// (bits == satval). Only an exact N x 256 strip of scores is needed; rows
// with <20 saturated strip entries go to an exact full-row fallback.
//
// Round-7 lesson: zero-fill BW is LOCALITY-sensitive, not instruction-
// sensitive. Grid-stride STG / memset / TMA chunking all hit ~2.5 TB/s
// (2MB-page hop per warp-iteration); contiguous per-CTA blocks hit ~4 TB/s
// (round 4). This round's writer: 1250 CTAs x contiguous 320KB blocks,
// sequential walk, streaming stores.
//
//   main stream:  prep -> strip ---------------+-> scatter -> fallback
//   fork stream:  zero_blk (contiguous) -------+   (join via event)
// ---------------------------------------------------------------------------

#define MAX_NPAD 10112

__device__ float g_Xt[128 * MAX_NPAD];     // [k][i]  X = [vec1 | -gEmb]
__device__ float g_Yt[128 * MAX_NPAD];     // [k][i]  Y = [gEmb  |  vec1]
__device__ unsigned g_maskS[MAX_NPAD * 8]; // strip tie bitmask (256 cols/row)
__device__ int g_fb_cnt;
__device__ int g_fb_list[MAX_NPAD];

__device__ __forceinline__ float tanh_xla(float x) {
    const float kClamp = 7.99881172180175781f;
    float ax = fabsf(x);
    float xc = fminf(fmaxf(x, -kClamp), kClamp);
    float x2 = xc * xc;
    float p = -2.76076847742355e-16f;
    p = fmaf(x2, p, 2.00018790482477e-13f);
    p = fmaf(x2, p, -8.60467152213735e-11f);
    p = fmaf(x2, p, 5.12229709037114e-08f);
    p = fmaf(x2, p, 1.48572235717979e-05f);
    p = fmaf(x2, p, 6.37261928875436e-04f);
    p = fmaf(x2, p, 4.89352455891786e-03f);
    p = xc * p;
    float q = fmaf(x2, 1.19825839466702e-06f, 1.18534705686654e-04f);
    q = fmaf(x2, q, 2.26843463243900e-03f);
    q = fmaf(x2, q, 4.89352518554385e-03f);
    float r = p / q;
    return (ax < 0.0004f) ? x : r;
}

__device__ __forceinline__ float sat_val() { return tanh_xla(8.0f); }

__device__ __forceinline__ void cp_async16(uint32_t saddr, const void* gaddr) {
    asm volatile("cp.async.cg.shared.global [%0], [%1], 16;" ::
                 "r"(saddr), "l"(gaddr));
}

// ---------------------------------------------------------------------------
// zero_blk: each CTA zeroes ONE contiguous block (page-local sequential walk,
// the round-4 pattern that measured ~4 TB/s). Streaming stores keep L2 clean
// for the concurrently-running strip kernel.
// ---------------------------------------------------------------------------
__global__ __launch_bounds__(256) void zero_blk_kernel(float4* __restrict__ out,
                                                       size_t n4,
                                                       size_t per_cta) {
    const float4 z = make_float4(0.0f, 0.0f, 0.0f, 0.0f);
    size_t base = (size_t)blockIdx.x * per_cta;
    size_t end = base + per_cta;
    if (end > n4) end = n4;
    for (size_t i = base + threadIdx.x; i < end; i += 256)
        __stcs(&out[i], z);
}

__global__ void zero_tail_kernel(float* __restrict__ out, size_t from,
                                 size_t total) {
    size_t i = from + blockIdx.x * blockDim.x + threadIdx.x;
    if (i < total) out[i] = 0.0f;
}

// ---------------------------------------------------------------------------
// prep: 64 rows per block; vec1 via smem-resident fc1_w^T; coalesced
// transposed packing of Xt/Yt through smem. Zeroes fallback counter.
// ---------------------------------------------------------------------------
__global__ __launch_bounds__(256) void prep_kernel(
    const int* __restrict__ idx, const float* __restrict__ gEmb,
    const float* __restrict__ embW, const float* __restrict__ fc1w,
    const float* __restrict__ fc1b, int N, int npad) {
    __shared__ float ws[64 * 65];   // phase A: fc1w^T; phase B/C: gEmb
    __shared__ float sv[64 * 65];   // vec1 transposed [d][i_local]
    __shared__ float bs[64];
    const int t = threadIdx.x;
    const int bi0 = blockIdx.x * 64;

    if (blockIdx.x == 0 && t == 0) g_fb_cnt = 0;

    for (int e = t; e < 64 * 64; e += 256) {
        int d = e >> 6, k = e & 63;
        ws[k * 65 + d] = fc1w[e];
    }
    if (t < 64) bs[t] = fc1b[t];
    __syncthreads();

    const int d = t & 63;
    const int rq = t >> 6;
#pragma unroll
    for (int rr = 0; rr < 16; rr++) {
        int il = rr * 4 + rq;
        int i = bi0 + il;
        float v = 0.0f;
        if (i < N) {
            int src = idx[i];
            const float* er = embW + (size_t)src * 64;
            float acc = 0.0f;
#pragma unroll
            for (int k = 0; k < 64; k++) acc = fmaf(er[k], ws[k * 65 + d], acc);
            acc += bs[d];
            v = tanh_xla(3.0f * acc);
        }
        sv[d * 65 + il] = v;
    }
    __syncthreads();

#pragma unroll
    for (int rr = 0; rr < 16; rr++) {
        int il = rr * 4 + rq;
        int i = bi0 + il;
        float g = (i < N) ? gEmb[(size_t)i * 64 + d] : 0.0f;
        ws[d * 65 + il] = g;
    }
    __syncthreads();

#pragma unroll
    for (int p = 0; p < 8; p++) {
        int e = p * 256 + t;
        int dd = e >> 4;
        int i4 = (e & 15) * 4;
        float4 xv, yv;
        if (dd < 64) {
            xv.x = sv[dd * 65 + i4 + 0]; xv.y = sv[dd * 65 + i4 + 1];
            xv.z = sv[dd * 65 + i4 + 2]; xv.w = sv[dd * 65 + i4 + 3];
            yv.x = ws[dd * 65 + i4 + 0]; yv.y = ws[dd * 65 + i4 + 1];
            yv.z = ws[dd * 65 + i4 + 2]; yv.w = ws[dd * 65 + i4 + 3];
        } else {
            int dl = dd - 64;
            xv.x = -ws[dl * 65 + i4 + 0]; xv.y = -ws[dl * 65 + i4 + 1];
            xv.z = -ws[dl * 65 + i4 + 2]; xv.w = -ws[dl * 65 + i4 + 3];
            yv.x = sv[dl * 65 + i4 + 0];  yv.y = sv[dl * 65 + i4 + 1];
            yv.z = sv[dl * 65 + i4 + 2];  yv.w = sv[dl * 65 + i4 + 3];
        }
        *(float4*)&g_Xt[(size_t)dd * npad + bi0 + i4] = xv;
        *(float4*)&g_Yt[(size_t)dd * npad + bi0 + i4] = yv;
    }
}

// ---------------------------------------------------------------------------
// strip: 64 rows x 128 cols per CTA, grid (2, npad/64). Whole K=128 in smem.
// Per-element k-ascending fp32 fmaf chain, bit-identical to prior rounds.
// Emits saturation bitmask words (cols bn..bn+127 -> words (bn>>5)..+3).
// ---------------------------------------------------------------------------
__global__ __launch_bounds__(256, 2) void strip_kernel(int npad) {
    const int bm = blockIdx.y * 64;
    const int bn = blockIdx.x * 128;

    extern __shared__ float sm[];
    float* Asf = sm;           // [k][r] 128 x 64
    float* Bsf = sm + 8192;    // [k][r] 128 x 128

    const int t = threadIdx.x;
    const int tx = t & 15, ty = t >> 4;

    {
        const float4* Xv = reinterpret_cast<const float4*>(g_Xt);
        const float4* Yv = reinterpret_cast<const float4*>(g_Yt);
        uint32_t As_s = (uint32_t)__cvta_generic_to_shared(Asf);
        uint32_t Bs_s = (uint32_t)__cvta_generic_to_shared(Bsf);
        const int np4 = npad >> 2;
        const int bm4 = bm >> 2, bn4 = bn >> 2;
#pragma unroll
        for (int e = 0; e < 8; e++) {
            int q = e * 256 + t;      // 0..2047
            int k = q >> 4;           // 0..127
            int r4 = q & 15;
            cp_async16(As_s + q * 16, &Xv[(size_t)k * np4 + bm4 + r4]);
        }
#pragma unroll
        for (int e = 0; e < 16; e++) {
            int q = e * 256 + t;      // 0..4095
            int k = q >> 5;
            int r4 = q & 31;
            cp_async16(Bs_s + q * 16, &Yv[(size_t)k * np4 + bn4 + r4]);
        }
        asm volatile("cp.async.commit_group;");
        asm volatile("cp.async.wait_group 0;");
    }
    __syncthreads();

    float acc[4][8];
#pragma unroll
    for (int i = 0; i < 4; i++)
#pragma unroll
        for (int j = 0; j < 8; j++) acc[i][j] = 0.0f;

#pragma unroll 4
    for (int k = 0; k < 128; k++) {
        const float* ak = Asf + k * 64;
        const float* bk = Bsf + k * 128;
        float4 a0 = *(const float4*)(ak + ty * 4);
        float4 b0 = *(const float4*)(bk + tx * 4);
        float4 b1 = *(const float4*)(bk + 64 + tx * 4);
        float ra[4] = {a0.x, a0.y, a0.z, a0.w};
        float rb[8] = {b0.x, b0.y, b0.z, b0.w, b1.x, b1.y, b1.z, b1.w};
#pragma unroll
        for (int i = 0; i < 4; i++)
#pragma unroll
            for (int j = 0; j < 8; j++)
                acc[i][j] = fmaf(ra[i], rb[j], acc[i][j]);
    }

#pragma unroll
    for (int i = 0; i < 4; i++)
#pragma unroll
        for (int j = 0; j < 8; j++) acc[i][j] = tanh_xla(3.0f * acc[i][j]);

    __syncthreads();  // As/Bs dead

    unsigned* mUw = reinterpret_cast<unsigned*>(sm);  // [64][32] nibbles
    const unsigned satb = __float_as_uint(sat_val());

#pragma unroll
    for (int ii = 0; ii < 4; ii++) {
        int r = ty * 4 + ii;
#pragma unroll
        for (int q = 0; q < 2; q++) {
            unsigned nib = 0;
#pragma unroll
            for (int b = 0; b < 4; b++)
                nib |= (__float_as_uint(acc[ii][q * 4 + b]) == satb) << b;
            mUw[r * 32 + 16 * q + tx] = nib;
        }
    }
    __syncthreads();

    {
        int r = t >> 2, ww = t & 3;
        unsigned wd = 0;
#pragma unroll
        for (int b = 0; b < 8; b++) wd |= mUw[r * 32 + ww * 8 + b] << (4 * b);
        g_maskS[(size_t)(bm + r) * 8 + (bn >> 5) + ww] = wd;
    }
}

// ---------------------------------------------------------------------------
// topk_scatter: warp per row. Scatter satval at the 20 smallest set bits of
// the 256-col strip mask into the (pre-zeroed) row. <20 -> fallback list.
// ---------------------------------------------------------------------------
__global__ __launch_bounds__(256) void topk_scatter_kernel(
    float* __restrict__ out, int N) {
    const int row = blockIdx.x * 8 + (threadIdx.x >> 5);
    const int lane = threadIdx.x & 31;
    if (row >= N) return;

    unsigned w = (lane < 8) ? g_maskS[(size_t)row * 8 + lane] : 0u;
    int c = __popc(w);
    int incl = c;
#pragma unroll
    for (int s = 1; s < 32; s <<= 1) {
        int o = __shfl_up_sync(0xffffffffu, incl, s);
        if (lane >= s) incl += o;
    }
    int excl = incl - c;
    int total = __shfl_sync(0xffffffffu, incl, 31);

    if (total >= 20) {
        const float sv = sat_val();
        float* rowp = out + (size_t)row * N;
        int base = excl;
        unsigned ww = w;
        while (ww && base < 20) {
            int b = __ffs(ww) - 1;
            ww &= ww - 1;
            rowp[lane * 32 + b] = sv;
            base++;
        }
    } else if (lane == 0) {
        int p = atomicAdd(&g_fb_cnt, 1);
        g_fb_list[p] = row;
    }
}

// ---------------------------------------------------------------------------
// fallback: exact full-row recompute + general top-20 (expected 0 rows).
// ---------------------------------------------------------------------------
__global__ __launch_bounds__(256) void fallback_kernel(float* __restrict__ out,
                                                       int N, int npad) {
    __shared__ float sX[128];
    __shared__ __align__(16) float srow[10016];
    __shared__ unsigned long long red[256];
    __shared__ int selIdx[20];
    __shared__ float selVal[20];

    const int t = threadIdx.x;
    const int cnt = g_fb_cnt;

    for (int ri = blockIdx.x; ri < cnt; ri += gridDim.x) {
        const int row = g_fb_list[ri];
        if (t < 128) sX[t] = g_Xt[(size_t)t * npad + row];
        __syncthreads();

        for (int j = t; j < N; j += 256) {
            float a = 0.0f;
#pragma unroll 4
            for (int k = 0; k < 128; k++)
                a = fmaf(sX[k], g_Yt[(size_t)k * npad + j], a);
            srow[j] = fmaxf(tanh_xla(3.0f * a), 0.0f);
        }
        __syncthreads();

        unsigned long long cand[20];
#pragma unroll
        for (int c = 0; c < 20; c++) cand[c] = 0ull;
        unsigned long long curMin = 0ull;
        for (int q = t; q < N; q += 256) {
            unsigned vb = __float_as_uint(srow[q]);
            if (vb == 0x80000000u) vb = 0u;
            unsigned long long key =
                ((unsigned long long)vb << 32) |
                (unsigned long long)(0xFFFFFFFFu - (unsigned)q);
            if (key > curMin) {
                bool done = false;
#pragma unroll
                for (int c = 0; c < 20; c++) {
                    if (!done && cand[c] == curMin) {
                        cand[c] = key;
                        done = true;
                    }
                }
                unsigned long long m = cand[0];
#pragma unroll
                for (int c = 1; c < 20; c++) m = (cand[c] < m) ? cand[c] : m;
                curMin = m;
            }
        }
        for (int it = 0; it < 20; it++) {
            unsigned long long m = cand[0];
#pragma unroll
            for (int c = 1; c < 20; c++) m = (cand[c] > m) ? cand[c] : m;
            red[t] = m;
            __syncthreads();
            for (int s = 128; s >= 32; s >>= 1) {
                if (t < s) {
                    unsigned long long o = red[t + s];
                    if (o > red[t]) red[t] = o;
                }
                __syncthreads();
            }
            if (t < 32) {
                unsigned long long g = red[t];
#pragma unroll
                for (int s = 16; s; s >>= 1) {
                    unsigned long long o = __shfl_xor_sync(0xffffffffu, g, s);
                    if (o > g) g = o;
                }
                if (t == 0) red[0] = g;
            }
            __syncthreads();
            unsigned long long g = red[0];
            if (t == 0) {
                if (g != 0ull) {
                    selIdx[it] =
                        (int)(0xFFFFFFFFu - (unsigned)(g & 0xFFFFFFFFull));
                    selVal[it] = __uint_as_float((unsigned)(g >> 32));
                } else {
                    selIdx[it] = 0;
                    selVal[it] = 0.0f;
                }
            }
            if (g != 0ull) {
#pragma unroll
                for (int c = 0; c < 20; c++)
                    if (cand[c] == g) cand[c] = 0ull;
            }
            __syncthreads();
        }
        if (t < 20) out[(size_t)row * N + selIdx[t]] = selVal[t];
        __syncthreads();
    }
}

// ---------------------------------------------------------------------------
extern "C" void kernel_launch(void* const* d_in, const int* in_sizes, int n_in,
                              void* d_out, int out_size) {
    const int* idx = (const int*)d_in[0];
    const float* gEmb = (const float*)d_in[1];
    const float* embW = (const float*)d_in[2];
    const float* fc1w = (const float*)d_in[3];
    const float* fc1b = (const float*)d_in[4];
    float* out = (float*)d_out;

    int N = in_sizes[0];
    int npad = ((N + 127) / 128) * 128;
    int tiles64 = npad / 64;
    size_t total = (size_t)out_size;
    size_t n4 = total >> 2;

    const int ZCTAS = 1250;
    size_t per_cta = (n4 + ZCTAS - 1) / ZCTAS;

    static cudaStream_t s_fork = nullptr;
    static cudaEvent_t s_evFork = nullptr, s_evJoin = nullptr;
    static bool s_init = false;
    if (!s_init) {
        cudaFuncSetAttribute(strip_kernel,
                             cudaFuncAttributeMaxDynamicSharedMemorySize,
                             98304);
        cudaStreamCreateWithFlags(&s_fork, cudaStreamNonBlocking);
        cudaEventCreateWithFlags(&s_evFork, cudaEventDisableTiming);
        cudaEventCreateWithFlags(&s_evJoin, cudaEventDisableTiming);
        s_init = true;
    }

    // fork: zero d_out (contiguous per-CTA blocks) on side stream,
    // overlapping prep + strip on the main stream
    cudaEventRecord(s_evFork, 0);
    cudaStreamWaitEvent(s_fork, s_evFork, 0);
    zero_blk_kernel<<<ZCTAS, 256, 0, s_fork>>>((float4*)out, n4, per_cta);
    if (total & 3) {
        zero_tail_kernel<<<1, 256, 0, s_fork>>>(out, n4 * 4, total);
    }
    cudaEventRecord(s_evJoin, s_fork);

    prep_kernel<<<npad / 64, 256>>>(idx, gEmb, embW, fc1w, fc1b, N, npad);
    strip_kernel<<<dim3(2, tiles64), 256, 98304>>>(npad);

    // join: scatter needs the zeroed buffer
    cudaStreamWaitEvent(0, s_evJoin, 0);
    topk_scatter_kernel<<<(N + 7) / 8, 256>>>(out, N);
    fallback_kernel<<<148, 256>>>(out, N, npad);
}

// round 9
// speedup vs baseline: 1.3303x; 1.2040x over previous
#include <cuda_runtime.h>
#include <cstdint>

// ---------------------------------------------------------------------------
// local_graph_creator: adj = relu(tanh(3*(vec1@gEmb.T - gEmb@vec1.T))),
// per-row top-20 (value desc, index asc) binary mask applied.
//
// Exact-output structure (rel_err == 0.0 across rounds 1-8): each output row
// is zeros plus satval at the 20 smallest column indices whose tanh saturates
// (bits == satval). Only an exact N x 256 strip of scores is needed; rows
// with <20 saturated strip entries go to an exact full-row fallback.
//
// Round-8 lesson: the SAME writer shape runs ~4.0 TB/s on the default stream
// (round 4, fused) but ~2.8 TB/s on the fork stream. This round swaps the
// branch assignment: the 400MB zero (round-4's exact warp-per-row plain-store
// writer) runs on the DEFAULT stream; prep+strip run on the fork stream.
//
//   main stream:  zero_rows (warp/row, plain STG) --+-> scatter -> fallback
//   fork stream:  prep -> strip --------------------+   (join via event)
// ---------------------------------------------------------------------------

#define MAX_NPAD 10112

__device__ float g_Xt[128 * MAX_NPAD];     // [k][i]  X = [vec1 | -gEmb]
__device__ float g_Yt[128 * MAX_NPAD];     // [k][i]  Y = [gEmb  |  vec1]
__device__ unsigned g_maskS[MAX_NPAD * 8]; // strip tie bitmask (256 cols/row)
__device__ int g_fb_cnt;
__device__ int g_fb_list[MAX_NPAD];

__device__ __forceinline__ float tanh_xla(float x) {
    const float kClamp = 7.99881172180175781f;
    float ax = fabsf(x);
    float xc = fminf(fmaxf(x, -kClamp), kClamp);
    float x2 = xc * xc;
    float p = -2.76076847742355e-16f;
    p = fmaf(x2, p, 2.00018790482477e-13f);
    p = fmaf(x2, p, -8.60467152213735e-11f);
    p = fmaf(x2, p, 5.12229709037114e-08f);
    p = fmaf(x2, p, 1.48572235717979e-05f);
    p = fmaf(x2, p, 6.37261928875436e-04f);
    p = fmaf(x2, p, 4.89352455891786e-03f);
    p = xc * p;
    float q = fmaf(x2, 1.19825839466702e-06f, 1.18534705686654e-04f);
    q = fmaf(x2, q, 2.26843463243900e-03f);
    q = fmaf(x2, q, 4.89352518554385e-03f);
    float r = p / q;
    return (ax < 0.0004f) ? x : r;
}

__device__ __forceinline__ float sat_val() { return tanh_xla(8.0f); }

__device__ __forceinline__ void cp_async16(uint32_t saddr, const void* gaddr) {
    asm volatile("cp.async.cg.shared.global [%0], [%1], 16;" ::
                 "r"(saddr), "l"(gaddr));
}

// ---------------------------------------------------------------------------
// zero_rows: EXACT round-4 writer shape (the one that measured ~4.0 TB/s):
// warp per row, 8 rows per CTA, plain float4 stores, lane-strided walk of a
// contiguous 40KB row.
// ---------------------------------------------------------------------------
__global__ __launch_bounds__(256) void zero_rows_kernel(float* __restrict__ out,
                                                        int N) {
    const int row = blockIdx.x * 8 + (threadIdx.x >> 5);
    const int lane = threadIdx.x & 31;
    if (row >= N) return;
    float* rowp = out + (size_t)row * N;
    const int nv = N >> 2;
    const float4 z = make_float4(0.0f, 0.0f, 0.0f, 0.0f);
    for (int q = lane; q < nv; q += 32) reinterpret_cast<float4*>(rowp)[q] = z;
    for (int q = nv * 4 + lane; q < N; q += 32) rowp[q] = 0.0f;
}

// ---------------------------------------------------------------------------
// prep: 64 rows per block; vec1 via smem-resident fc1_w^T; coalesced
// transposed packing of Xt/Yt through smem. Zeroes fallback counter.
// ---------------------------------------------------------------------------
__global__ __launch_bounds__(256) void prep_kernel(
    const int* __restrict__ idx, const float* __restrict__ gEmb,
    const float* __restrict__ embW, const float* __restrict__ fc1w,
    const float* __restrict__ fc1b, int N, int npad) {
    __shared__ float ws[64 * 65];   // phase A: fc1w^T; phase B/C: gEmb
    __shared__ float sv[64 * 65];   // vec1 transposed [d][i_local]
    __shared__ float bs[64];
    const int t = threadIdx.x;
    const int bi0 = blockIdx.x * 64;

    if (blockIdx.x == 0 && t == 0) g_fb_cnt = 0;

    for (int e = t; e < 64 * 64; e += 256) {
        int d = e >> 6, k = e & 63;
        ws[k * 65 + d] = fc1w[e];
    }
    if (t < 64) bs[t] = fc1b[t];
    __syncthreads();

    const int d = t & 63;
    const int rq = t >> 6;
#pragma unroll
    for (int rr = 0; rr < 16; rr++) {
        int il = rr * 4 + rq;
        int i = bi0 + il;
        float v = 0.0f;
        if (i < N) {
            int src = idx[i];
            const float* er = embW + (size_t)src * 64;
            float acc = 0.0f;
#pragma unroll
            for (int k = 0; k < 64; k++) acc = fmaf(er[k], ws[k * 65 + d], acc);
            acc += bs[d];
            v = tanh_xla(3.0f * acc);
        }
        sv[d * 65 + il] = v;
    }
    __syncthreads();

#pragma unroll
    for (int rr = 0; rr < 16; rr++) {
        int il = rr * 4 + rq;
        int i = bi0 + il;
        float g = (i < N) ? gEmb[(size_t)i * 64 + d] : 0.0f;
        ws[d * 65 + il] = g;
    }
    __syncthreads();

#pragma unroll
    for (int p = 0; p < 8; p++) {
        int e = p * 256 + t;
        int dd = e >> 4;
        int i4 = (e & 15) * 4;
        float4 xv, yv;
        if (dd < 64) {
            xv.x = sv[dd * 65 + i4 + 0]; xv.y = sv[dd * 65 + i4 + 1];
            xv.z = sv[dd * 65 + i4 + 2]; xv.w = sv[dd * 65 + i4 + 3];
            yv.x = ws[dd * 65 + i4 + 0]; yv.y = ws[dd * 65 + i4 + 1];
            yv.z = ws[dd * 65 + i4 + 2]; yv.w = ws[dd * 65 + i4 + 3];
        } else {
            int dl = dd - 64;
            xv.x = -ws[dl * 65 + i4 + 0]; xv.y = -ws[dl * 65 + i4 + 1];
            xv.z = -ws[dl * 65 + i4 + 2]; xv.w = -ws[dl * 65 + i4 + 3];
            yv.x = sv[dl * 65 + i4 + 0];  yv.y = sv[dl * 65 + i4 + 1];
            yv.z = sv[dl * 65 + i4 + 2];  yv.w = sv[dl * 65 + i4 + 3];
        }
        *(float4*)&g_Xt[(size_t)dd * npad + bi0 + i4] = xv;
        *(float4*)&g_Yt[(size_t)dd * npad + bi0 + i4] = yv;
    }
}

// ---------------------------------------------------------------------------
// strip: 64 rows x 128 cols per CTA, grid (2, npad/64). Whole K=128 in smem.
// Per-element k-ascending fp32 fmaf chain, bit-identical to prior rounds.
// Emits saturation bitmask words (cols bn..bn+127 -> words (bn>>5)..+3).
// ---------------------------------------------------------------------------
__global__ __launch_bounds__(256, 2) void strip_kernel(int npad) {
    const int bm = blockIdx.y * 64;
    const int bn = blockIdx.x * 128;

    extern __shared__ float sm[];
    float* Asf = sm;           // [k][r] 128 x 64
    float* Bsf = sm + 8192;    // [k][r] 128 x 128

    const int t = threadIdx.x;
    const int tx = t & 15, ty = t >> 4;

    {
        const float4* Xv = reinterpret_cast<const float4*>(g_Xt);
        const float4* Yv = reinterpret_cast<const float4*>(g_Yt);
        uint32_t As_s = (uint32_t)__cvta_generic_to_shared(Asf);
        uint32_t Bs_s = (uint32_t)__cvta_generic_to_shared(Bsf);
        const int np4 = npad >> 2;
        const int bm4 = bm >> 2, bn4 = bn >> 2;
#pragma unroll
        for (int e = 0; e < 8; e++) {
            int q = e * 256 + t;      // 0..2047
            int k = q >> 4;           // 0..127
            int r4 = q & 15;
            cp_async16(As_s + q * 16, &Xv[(size_t)k * np4 + bm4 + r4]);
        }
#pragma unroll
        for (int e = 0; e < 16; e++) {
            int q = e * 256 + t;      // 0..4095
            int k = q >> 5;
            int r4 = q & 31;
            cp_async16(Bs_s + q * 16, &Yv[(size_t)k * np4 + bn4 + r4]);
        }
        asm volatile("cp.async.commit_group;");
        asm volatile("cp.async.wait_group 0;");
    }
    __syncthreads();

    float acc[4][8];
#pragma unroll
    for (int i = 0; i < 4; i++)
#pragma unroll
        for (int j = 0; j < 8; j++) acc[i][j] = 0.0f;

#pragma unroll 4
    for (int k = 0; k < 128; k++) {
        const float* ak = Asf + k * 64;
        const float* bk = Bsf + k * 128;
        float4 a0 = *(const float4*)(ak + ty * 4);
        float4 b0 = *(const float4*)(bk + tx * 4);
        float4 b1 = *(const float4*)(bk + 64 + tx * 4);
        float ra[4] = {a0.x, a0.y, a0.z, a0.w};
        float rb[8] = {b0.x, b0.y, b0.z, b0.w, b1.x, b1.y, b1.z, b1.w};
#pragma unroll
        for (int i = 0; i < 4; i++)
#pragma unroll
            for (int j = 0; j < 8; j++)
                acc[i][j] = fmaf(ra[i], rb[j], acc[i][j]);
    }

#pragma unroll
    for (int i = 0; i < 4; i++)
#pragma unroll
        for (int j = 0; j < 8; j++) acc[i][j] = tanh_xla(3.0f * acc[i][j]);

    __syncthreads();  // As/Bs dead

    unsigned* mUw = reinterpret_cast<unsigned*>(sm);  // [64][32] nibbles
    const unsigned satb = __float_as_uint(sat_val());

#pragma unroll
    for (int ii = 0; ii < 4; ii++) {
        int r = ty * 4 + ii;
#pragma unroll
        for (int q = 0; q < 2; q++) {
            unsigned nib = 0;
#pragma unroll
            for (int b = 0; b < 4; b++)
                nib |= (__float_as_uint(acc[ii][q * 4 + b]) == satb) << b;
            mUw[r * 32 + 16 * q + tx] = nib;
        }
    }
    __syncthreads();

    {
        int r = t >> 2, ww = t & 3;
        unsigned wd = 0;
#pragma unroll
        for (int b = 0; b < 8; b++) wd |= mUw[r * 32 + ww * 8 + b] << (4 * b);
        g_maskS[(size_t)(bm + r) * 8 + (bn >> 5) + ww] = wd;
    }
}

// ---------------------------------------------------------------------------
// topk_scatter: warp per row. Scatter satval at the 20 smallest set bits of
// the 256-col strip mask into the (pre-zeroed) row. <20 -> fallback list.
// ---------------------------------------------------------------------------
__global__ __launch_bounds__(256) void topk_scatter_kernel(
    float* __restrict__ out, int N) {
    const int row = blockIdx.x * 8 + (threadIdx.x >> 5);
    const int lane = threadIdx.x & 31;
    if (row >= N) return;

    unsigned w = (lane < 8) ? g_maskS[(size_t)row * 8 + lane] : 0u;
    int c = __popc(w);
    int incl = c;
#pragma unroll
    for (int s = 1; s < 32; s <<= 1) {
        int o = __shfl_up_sync(0xffffffffu, incl, s);
        if (lane >= s) incl += o;
    }
    int excl = incl - c;
    int total = __shfl_sync(0xffffffffu, incl, 31);

    if (total >= 20) {
        const float sv = sat_val();
        float* rowp = out + (size_t)row * N;
        int base = excl;
        unsigned ww = w;
        while (ww && base < 20) {
            int b = __ffs(ww) - 1;
            ww &= ww - 1;
            rowp[lane * 32 + b] = sv;
            base++;
        }
    } else if (lane == 0) {
        int p = atomicAdd(&g_fb_cnt, 1);
        g_fb_list[p] = row;
    }
}

// ---------------------------------------------------------------------------
// fallback: exact full-row recompute + general top-20 (expected 0 rows).
// ---------------------------------------------------------------------------
__global__ __launch_bounds__(256) void fallback_kernel(float* __restrict__ out,
                                                       int N, int npad) {
    __shared__ float sX[128];
    __shared__ __align__(16) float srow[10016];
    __shared__ unsigned long long red[256];
    __shared__ int selIdx[20];
    __shared__ float selVal[20];

    const int t = threadIdx.x;
    const int cnt = g_fb_cnt;

    for (int ri = blockIdx.x; ri < cnt; ri += gridDim.x) {
        const int row = g_fb_list[ri];
        if (t < 128) sX[t] = g_Xt[(size_t)t * npad + row];
        __syncthreads();

        for (int j = t; j < N; j += 256) {
            float a = 0.0f;
#pragma unroll 4
            for (int k = 0; k < 128; k++)
                a = fmaf(sX[k], g_Yt[(size_t)k * npad + j], a);
            srow[j] = fmaxf(tanh_xla(3.0f * a), 0.0f);
        }
        __syncthreads();

        unsigned long long cand[20];
#pragma unroll
        for (int c = 0; c < 20; c++) cand[c] = 0ull;
        unsigned long long curMin = 0ull;
        for (int q = t; q < N; q += 256) {
            unsigned vb = __float_as_uint(srow[q]);
            if (vb == 0x80000000u) vb = 0u;
            unsigned long long key =
                ((unsigned long long)vb << 32) |
                (unsigned long long)(0xFFFFFFFFu - (unsigned)q);
            if (key > curMin) {
                bool done = false;
#pragma unroll
                for (int c = 0; c < 20; c++) {
                    if (!done && cand[c] == curMin) {
                        cand[c] = key;
                        done = true;
                    }
                }
                unsigned long long m = cand[0];
#pragma unroll
                for (int c = 1; c < 20; c++) m = (cand[c] < m) ? cand[c] : m;
                curMin = m;
            }
        }
        for (int it = 0; it < 20; it++) {
            unsigned long long m = cand[0];
#pragma unroll
            for (int c = 1; c < 20; c++) m = (cand[c] > m) ? cand[c] : m;
            red[t] = m;
            __syncthreads();
            for (int s = 128; s >= 32; s >>= 1) {
                if (t < s) {
                    unsigned long long o = red[t + s];
                    if (o > red[t]) red[t] = o;
                }
                __syncthreads();
            }
            if (t < 32) {
                unsigned long long g = red[t];
#pragma unroll
                for (int s = 16; s; s >>= 1) {
                    unsigned long long o = __shfl_xor_sync(0xffffffffu, g, s);
                    if (o > g) g = o;
                }
                if (t == 0) red[0] = g;
            }
            __syncthreads();
            unsigned long long g = red[0];
            if (t == 0) {
                if (g != 0ull) {
                    selIdx[it] =
                        (int)(0xFFFFFFFFu - (unsigned)(g & 0xFFFFFFFFull));
                    selVal[it] = __uint_as_float((unsigned)(g >> 32));
                } else {
                    selIdx[it] = 0;
                    selVal[it] = 0.0f;
                }
            }
            if (g != 0ull) {
#pragma unroll
                for (int c = 0; c < 20; c++)
                    if (cand[c] == g) cand[c] = 0ull;
            }
            __syncthreads();
        }
        if (t < 20) out[(size_t)row * N + selIdx[t]] = selVal[t];
        __syncthreads();
    }
}

// ---------------------------------------------------------------------------
extern "C" void kernel_launch(void* const* d_in, const int* in_sizes, int n_in,
                              void* d_out, int out_size) {
    const int* idx = (const int*)d_in[0];
    const float* gEmb = (const float*)d_in[1];
    const float* embW = (const float*)d_in[2];
    const float* fc1w = (const float*)d_in[3];
    const float* fc1b = (const float*)d_in[4];
    float* out = (float*)d_out;

    int N = in_sizes[0];
    int npad = ((N + 127) / 128) * 128;
    int tiles64 = npad / 64;

    static cudaStream_t s_fork = nullptr;
    static cudaEvent_t s_evFork = nullptr, s_evJoin = nullptr;
    static bool s_init = false;
    if (!s_init) {
        cudaFuncSetAttribute(strip_kernel,
                             cudaFuncAttributeMaxDynamicSharedMemorySize,
                             98304);
        cudaStreamCreateWithFlags(&s_fork, cudaStreamNonBlocking);
        cudaEventCreateWithFlags(&s_evFork, cudaEventDisableTiming);
        cudaEventCreateWithFlags(&s_evJoin, cudaEventDisableTiming);
        s_init = true;
    }

    // fork: prep + strip (small, independent of d_out) on the side stream
    cudaEventRecord(s_evFork, 0);
    cudaStreamWaitEvent(s_fork, s_evFork, 0);
    prep_kernel<<<npad / 64, 256, 0, s_fork>>>(idx, gEmb, embW, fc1w, fc1b, N,
                                               npad);
    strip_kernel<<<dim3(2, tiles64), 256, 98304, s_fork>>>(npad);
    cudaEventRecord(s_evJoin, s_fork);

    // main (default) stream: the big zero with the proven-fast writer
    zero_rows_kernel<<<(N + 7) / 8, 256>>>(out, N);

    // join: scatter needs both the zeroed buffer (main) and masks (fork)
    cudaStreamWaitEvent(0, s_evJoin, 0);
    topk_scatter_kernel<<<(N + 7) / 8, 256>>>(out, N);
    fallback_kernel<<<148, 256>>>(out, N, npad);
}

// round 10
// speedup vs baseline: 1.3735x; 1.0325x over previous
#include <cuda_runtime.h>
#include <cstdint>

// ---------------------------------------------------------------------------
// local_graph_creator: adj = relu(tanh(3*(vec1@gEmb.T - gEmb@vec1.T))),
// per-row top-20 (value desc, index asc) binary mask applied.
//
// Exact-output structure (rel_err == 0.0 across rounds 1-9): each output row
// is zeros plus satval at the 20 smallest column indices whose tanh saturates
// (bits == satval). Only an exact N x 256 strip of scores is needed; rows
// with <20 saturated strip entries go to an exact full-row fallback.
//
// Settled BW model: pure-write wall ~4 TB/s, reached only by contiguous
// per-warp rows on the DEFAULT stream (fork streams cap ~2.8 TB/s).
//
// This round: scatter targets are all in cols [0,256), so the big zero only
// covers cols [256,N); a fused finish kernel zeroes cols [0,256) + scatters,
// absorbing the separate scatter launch.
//
//   main stream:  zero_tailcols (cols 256..N) --+-> finish(zero0-256+scatter)
//   fork stream:  prep -> strip ----------------+       -> fallback
// ---------------------------------------------------------------------------

#define MAX_NPAD 10112
#define STRIPW 256

__device__ float g_Xt[128 * MAX_NPAD];     // [k][i]  X = [vec1 | -gEmb]
__device__ float g_Yt[128 * MAX_NPAD];     // [k][i]  Y = [gEmb  |  vec1]
__device__ unsigned g_maskS[MAX_NPAD * 8]; // strip tie bitmask (256 cols/row)
__device__ int g_fb_cnt;
__device__ int g_fb_list[MAX_NPAD];

__device__ __forceinline__ float tanh_xla(float x) {
    const float kClamp = 7.99881172180175781f;
    float ax = fabsf(x);
    float xc = fminf(fmaxf(x, -kClamp), kClamp);
    float x2 = xc * xc;
    float p = -2.76076847742355e-16f;
    p = fmaf(x2, p, 2.00018790482477e-13f);
    p = fmaf(x2, p, -8.60467152213735e-11f);
    p = fmaf(x2, p, 5.12229709037114e-08f);
    p = fmaf(x2, p, 1.48572235717979e-05f);
    p = fmaf(x2, p, 6.37261928875436e-04f);
    p = fmaf(x2, p, 4.89352455891786e-03f);
    p = xc * p;
    float q = fmaf(x2, 1.19825839466702e-06f, 1.18534705686654e-04f);
    q = fmaf(x2, q, 2.26843463243900e-03f);
    q = fmaf(x2, q, 4.89352518554385e-03f);
    float r = p / q;
    return (ax < 0.0004f) ? x : r;
}

__device__ __forceinline__ float sat_val() { return tanh_xla(8.0f); }

__device__ __forceinline__ void cp_async16(uint32_t saddr, const void* gaddr) {
    asm volatile("cp.async.cg.shared.global [%0], [%1], 16;" ::
                 "r"(saddr), "l"(gaddr));
}

// ---------------------------------------------------------------------------
// zero_tailcols: proven-fast writer shape (warp per row, 8 rows/CTA, plain
// float4 stores, default stream), restricted to cols [STRIPW, N).
// ---------------------------------------------------------------------------
__global__ __launch_bounds__(256) void zero_tailcols_kernel(
    float* __restrict__ out, int N) {
    const int row = blockIdx.x * 8 + (threadIdx.x >> 5);
    const int lane = threadIdx.x & 31;
    if (row >= N) return;
    if (N <= STRIPW) return;
    float* rowp = out + (size_t)row * N + STRIPW;
    const int len = N - STRIPW;        // floats to zero
    const int nv = len >> 2;
    const float4 z = make_float4(0.0f, 0.0f, 0.0f, 0.0f);
    for (int q = lane; q < nv; q += 32) reinterpret_cast<float4*>(rowp)[q] = z;
    for (int q = nv * 4 + lane; q < len; q += 32) rowp[q] = 0.0f;
}

// ---------------------------------------------------------------------------
// finish: warp per row. Zero cols [0, min(STRIPW,N)), then scatter satval at
// the 20 smallest set bits of the strip mask. <20 bits -> fallback list.
// ---------------------------------------------------------------------------
__global__ __launch_bounds__(256) void finish_kernel(float* __restrict__ out,
                                                     int N) {
    const int row = blockIdx.x * 8 + (threadIdx.x >> 5);
    const int lane = threadIdx.x & 31;
    if (row >= N) return;

    float* rowp = out + (size_t)row * N;
    const int head = (N < STRIPW) ? N : STRIPW;
    {
        const int nv = head >> 2;
        const float4 z = make_float4(0.0f, 0.0f, 0.0f, 0.0f);
        for (int q = lane; q < nv; q += 32)
            reinterpret_cast<float4*>(rowp)[q] = z;
        for (int q = nv * 4 + lane; q < head; q += 32) rowp[q] = 0.0f;
    }
    __syncwarp();

    unsigned w = (lane < 8) ? g_maskS[(size_t)row * 8 + lane] : 0u;
    int c = __popc(w);
    int incl = c;
#pragma unroll
    for (int s = 1; s < 32; s <<= 1) {
        int o = __shfl_up_sync(0xffffffffu, incl, s);
        if (lane >= s) incl += o;
    }
    int excl = incl - c;
    int total = __shfl_sync(0xffffffffu, incl, 31);

    if (total >= 20) {
        const float sv = sat_val();
        int base = excl;
        unsigned ww = w;
        while (ww && base < 20) {
            int b = __ffs(ww) - 1;
            ww &= ww - 1;
            rowp[lane * 32 + b] = sv;
            base++;
        }
    } else if (lane == 0) {
        int p = atomicAdd(&g_fb_cnt, 1);
        g_fb_list[p] = row;
    }
}

// ---------------------------------------------------------------------------
// prep: 64 rows per block; vec1 via smem-resident fc1_w^T; coalesced
// transposed packing of Xt/Yt through smem. Zeroes fallback counter.
// ---------------------------------------------------------------------------
__global__ __launch_bounds__(256) void prep_kernel(
    const int* __restrict__ idx, const float* __restrict__ gEmb,
    const float* __restrict__ embW, const float* __restrict__ fc1w,
    const float* __restrict__ fc1b, int N, int npad) {
    __shared__ float ws[64 * 65];   // phase A: fc1w^T; phase B/C: gEmb
    __shared__ float sv[64 * 65];   // vec1 transposed [d][i_local]
    __shared__ float bs[64];
    const int t = threadIdx.x;
    const int bi0 = blockIdx.x * 64;

    if (blockIdx.x == 0 && t == 0) g_fb_cnt = 0;

    for (int e = t; e < 64 * 64; e += 256) {
        int d = e >> 6, k = e & 63;
        ws[k * 65 + d] = fc1w[e];
    }
    if (t < 64) bs[t] = fc1b[t];
    __syncthreads();

    const int d = t & 63;
    const int rq = t >> 6;
#pragma unroll
    for (int rr = 0; rr < 16; rr++) {
        int il = rr * 4 + rq;
        int i = bi0 + il;
        float v = 0.0f;
        if (i < N) {
            int src = idx[i];
            const float* er = embW + (size_t)src * 64;
            float acc = 0.0f;
#pragma unroll
            for (int k = 0; k < 64; k++) acc = fmaf(er[k], ws[k * 65 + d], acc);
            acc += bs[d];
            v = tanh_xla(3.0f * acc);
        }
        sv[d * 65 + il] = v;
    }
    __syncthreads();

#pragma unroll
    for (int rr = 0; rr < 16; rr++) {
        int il = rr * 4 + rq;
        int i = bi0 + il;
        float g = (i < N) ? gEmb[(size_t)i * 64 + d] : 0.0f;
        ws[d * 65 + il] = g;
    }
    __syncthreads();

#pragma unroll
    for (int p = 0; p < 8; p++) {
        int e = p * 256 + t;
        int dd = e >> 4;
        int i4 = (e & 15) * 4;
        float4 xv, yv;
        if (dd < 64) {
            xv.x = sv[dd * 65 + i4 + 0]; xv.y = sv[dd * 65 + i4 + 1];
            xv.z = sv[dd * 65 + i4 + 2]; xv.w = sv[dd * 65 + i4 + 3];
            yv.x = ws[dd * 65 + i4 + 0]; yv.y = ws[dd * 65 + i4 + 1];
            yv.z = ws[dd * 65 + i4 + 2]; yv.w = ws[dd * 65 + i4 + 3];
        } else {
            int dl = dd - 64;
            xv.x = -ws[dl * 65 + i4 + 0]; xv.y = -ws[dl * 65 + i4 + 1];
            xv.z = -ws[dl * 65 + i4 + 2]; xv.w = -ws[dl * 65 + i4 + 3];
            yv.x = sv[dl * 65 + i4 + 0];  yv.y = sv[dl * 65 + i4 + 1];
            yv.z = sv[dl * 65 + i4 + 2];  yv.w = sv[dl * 65 + i4 + 3];
        }
        *(float4*)&g_Xt[(size_t)dd * npad + bi0 + i4] = xv;
        *(float4*)&g_Yt[(size_t)dd * npad + bi0 + i4] = yv;
    }
}

// ---------------------------------------------------------------------------
// strip: 64 rows x 128 cols per CTA, grid (2, npad/64). Whole K=128 in smem.
// Per-element k-ascending fp32 fmaf chain, bit-identical to prior rounds.
// Emits saturation bitmask words (cols bn..bn+127 -> words (bn>>5)..+3).
// ---------------------------------------------------------------------------
__global__ __launch_bounds__(256, 2) void strip_kernel(int npad) {
    const int bm = blockIdx.y * 64;
    const int bn = blockIdx.x * 128;

    extern __shared__ float sm[];
    float* Asf = sm;           // [k][r] 128 x 64
    float* Bsf = sm + 8192;    // [k][r] 128 x 128

    const int t = threadIdx.x;
    const int tx = t & 15, ty = t >> 4;

    {
        const float4* Xv = reinterpret_cast<const float4*>(g_Xt);
        const float4* Yv = reinterpret_cast<const float4*>(g_Yt);
        uint32_t As_s = (uint32_t)__cvta_generic_to_shared(Asf);
        uint32_t Bs_s = (uint32_t)__cvta_generic_to_shared(Bsf);
        const int np4 = npad >> 2;
        const int bm4 = bm >> 2, bn4 = bn >> 2;
#pragma unroll
        for (int e = 0; e < 8; e++) {
            int q = e * 256 + t;      // 0..2047
            int k = q >> 4;           // 0..127
            int r4 = q & 15;
            cp_async16(As_s + q * 16, &Xv[(size_t)k * np4 + bm4 + r4]);
        }
#pragma unroll
        for (int e = 0; e < 16; e++) {
            int q = e * 256 + t;      // 0..4095
            int k = q >> 5;
            int r4 = q & 31;
            cp_async16(Bs_s + q * 16, &Yv[(size_t)k * np4 + bn4 + r4]);
        }
        asm volatile("cp.async.commit_group;");
        asm volatile("cp.async.wait_group 0;");
    }
    __syncthreads();

    float acc[4][8];
#pragma unroll
    for (int i = 0; i < 4; i++)
#pragma unroll
        for (int j = 0; j < 8; j++) acc[i][j] = 0.0f;

#pragma unroll 4
    for (int k = 0; k < 128; k++) {
        const float* ak = Asf + k * 64;
        const float* bk = Bsf + k * 128;
        float4 a0 = *(const float4*)(ak + ty * 4);
        float4 b0 = *(const float4*)(bk + tx * 4);
        float4 b1 = *(const float4*)(bk + 64 + tx * 4);
        float ra[4] = {a0.x, a0.y, a0.z, a0.w};
        float rb[8] = {b0.x, b0.y, b0.z, b0.w, b1.x, b1.y, b1.z, b1.w};
#pragma unroll
        for (int i = 0; i < 4; i++)
#pragma unroll
            for (int j = 0; j < 8; j++)
                acc[i][j] = fmaf(ra[i], rb[j], acc[i][j]);
    }

#pragma unroll
    for (int i = 0; i < 4; i++)
#pragma unroll
        for (int j = 0; j < 8; j++) acc[i][j] = tanh_xla(3.0f * acc[i][j]);

    __syncthreads();  // As/Bs dead

    unsigned* mUw = reinterpret_cast<unsigned*>(sm);  // [64][32] nibbles
    const unsigned satb = __float_as_uint(sat_val());

#pragma unroll
    for (int ii = 0; ii < 4; ii++) {
        int r = ty * 4 + ii;
#pragma unroll
        for (int q = 0; q < 2; q++) {
            unsigned nib = 0;
#pragma unroll
            for (int b = 0; b < 4; b++)
                nib |= (__float_as_uint(acc[ii][q * 4 + b]) == satb) << b;
            mUw[r * 32 + 16 * q + tx] = nib;
        }
    }
    __syncthreads();

    {
        int r = t >> 2, ww = t & 3;
        unsigned wd = 0;
#pragma unroll
        for (int b = 0; b < 8; b++) wd |= mUw[r * 32 + ww * 8 + b] << (4 * b);
        g_maskS[(size_t)(bm + r) * 8 + (bn >> 5) + ww] = wd;
    }
}

// ---------------------------------------------------------------------------
// fallback: exact full-row recompute + general top-20 (expected 0 rows).
// ---------------------------------------------------------------------------
__global__ __launch_bounds__(256) void fallback_kernel(float* __restrict__ out,
                                                       int N, int npad) {
    __shared__ float sX[128];
    __shared__ __align__(16) float srow[10016];
    __shared__ unsigned long long red[256];
    __shared__ int selIdx[20];
    __shared__ float selVal[20];

    const int t = threadIdx.x;
    const int cnt = g_fb_cnt;

    for (int ri = blockIdx.x; ri < cnt; ri += gridDim.x) {
        const int row = g_fb_list[ri];
        if (t < 128) sX[t] = g_Xt[(size_t)t * npad + row];
        __syncthreads();

        for (int j = t; j < N; j += 256) {
            float a = 0.0f;
#pragma unroll 4
            for (int k = 0; k < 128; k++)
                a = fmaf(sX[k], g_Yt[(size_t)k * npad + j], a);
            srow[j] = fmaxf(tanh_xla(3.0f * a), 0.0f);
        }
        __syncthreads();

        unsigned long long cand[20];
#pragma unroll
        for (int c = 0; c < 20; c++) cand[c] = 0ull;
        unsigned long long curMin = 0ull;
        for (int q = t; q < N; q += 256) {
            unsigned vb = __float_as_uint(srow[q]);
            if (vb == 0x80000000u) vb = 0u;
            unsigned long long key =
                ((unsigned long long)vb << 32) |
                (unsigned long long)(0xFFFFFFFFu - (unsigned)q);
            if (key > curMin) {
                bool done = false;
#pragma unroll
                for (int c = 0; c < 20; c++) {
                    if (!done && cand[c] == curMin) {
                        cand[c] = key;
                        done = true;
                    }
                }
                unsigned long long m = cand[0];
#pragma unroll
                for (int c = 1; c < 20; c++) m = (cand[c] < m) ? cand[c] : m;
                curMin = m;
            }
        }
        for (int it = 0; it < 20; it++) {
            unsigned long long m = cand[0];
#pragma unroll
            for (int c = 1; c < 20; c++) m = (cand[c] > m) ? cand[c] : m;
            red[t] = m;
            __syncthreads();
            for (int s = 128; s >= 32; s >>= 1) {
                if (t < s) {
                    unsigned long long o = red[t + s];
                    if (o > red[t]) red[t] = o;
                }
                __syncthreads();
            }
            if (t < 32) {
                unsigned long long g = red[t];
#pragma unroll
                for (int s = 16; s; s >>= 1) {
                    unsigned long long o = __shfl_xor_sync(0xffffffffu, g, s);
                    if (o > g) g = o;
                }
                if (t == 0) red[0] = g;
            }
            __syncthreads();
            unsigned long long g = red[0];
            if (t == 0) {
                if (g != 0ull) {
                    selIdx[it] =
                        (int)(0xFFFFFFFFu - (unsigned)(g & 0xFFFFFFFFull));
                    selVal[it] = __uint_as_float((unsigned)(g >> 32));
                } else {
                    selIdx[it] = 0;
                    selVal[it] = 0.0f;
                }
            }
            if (g != 0ull) {
#pragma unroll
                for (int c = 0; c < 20; c++)
                    if (cand[c] == g) cand[c] = 0ull;
            }
            __syncthreads();
        }
        if (t < 20) out[(size_t)row * N + selIdx[t]] = selVal[t];
        __syncthreads();
    }
}

// ---------------------------------------------------------------------------
extern "C" void kernel_launch(void* const* d_in, const int* in_sizes, int n_in,
                              void* d_out, int out_size) {
    const int* idx = (const int*)d_in[0];
    const float* gEmb = (const float*)d_in[1];
    const float* embW = (const float*)d_in[2];
    const float* fc1w = (const float*)d_in[3];
    const float* fc1b = (const float*)d_in[4];
    float* out = (float*)d_out;

    int N = in_sizes[0];
    int npad = ((N + 127) / 128) * 128;
    int tiles64 = npad / 64;

    static cudaStream_t s_fork = nullptr;
    static cudaEvent_t s_evFork = nullptr, s_evJoin = nullptr;
    static bool s_init = false;
    if (!s_init) {
        cudaFuncSetAttribute(strip_kernel,
                             cudaFuncAttributeMaxDynamicSharedMemorySize,
                             98304);
        cudaStreamCreateWithFlags(&s_fork, cudaStreamNonBlocking);
        cudaEventCreateWithFlags(&s_evFork, cudaEventDisableTiming);
        cudaEventCreateWithFlags(&s_evJoin, cudaEventDisableTiming);
        s_init = true;
    }

    // fork: prep + strip (small, independent of d_out) on the side stream
    cudaEventRecord(s_evFork, 0);
    cudaStreamWaitEvent(s_fork, s_evFork, 0);
    prep_kernel<<<npad / 64, 256, 0, s_fork>>>(idx, gEmb, embW, fc1w, fc1b, N,
                                               npad);
    strip_kernel<<<dim3(2, tiles64), 256, 98304, s_fork>>>(npad);
    cudaEventRecord(s_evJoin, s_fork);

    // main (default) stream: big zero of cols [256, N) (proven-fast writer)
    zero_tailcols_kernel<<<(N + 7) / 8, 256>>>(out, N);

    // join: finish needs masks (fork) and runs after the big zero (main)
    cudaStreamWaitEvent(0, s_evJoin, 0);
    finish_kernel<<<(N + 7) / 8, 256>>>(out, N);
    fallback_kernel<<<16, 256>>>(out, N, npad);
}